// round 4
// baseline (speedup 1.0000x reference)
#include <cuda_runtime.h>
#include <cuda_bf16.h>
#include <cstdint>

#define Dd 256
#define HWc 1024
#define Kc 1024
#define NBLK 512
#define NTOT (64 * HWc)
#define CAP 20

__device__ float g_cn[Kc];
__device__ float g_dcn[Kc];
__device__ float g_partials[NBLK];
__device__ __nv_bfloat16 g_z0[(size_t)NTOT * Dd];
__device__ __nv_bfloat16 g_c0[Kc * Dd];

#define SWZ(x) ((x) ^ (((x) >> 3) & 0x70))

// smem offsets (relative to 1024-aligned base)
#define OFF_A    0         // 4 kc x (128 rows x 128B) = 65536
#define OFF_B    65536     // 2 bufs x 16384 = 32768
#define OFF_CN   98304     // 1024 f32 = 4096
#define OFF_DIST 102400    // 128 x 132 f32 = 67584
#define OFF_ZZ   169984    // 128 f32
#define OFF_RED  170496    // 256 f32
#define OFF_RM   171520    // 256 f32
#define OFF_CNT  172544    // 256 i32
#define OFF_LIST 173568    // 256 x CAP u16 = 10240
#define OFF_IDX  183808    // 128 i32
#define OFF_W    184320    // 128 f32
#define SMEM_BYTES (184832 + 1024)

__device__ __forceinline__ uint32_t smem_u32(const void* p) {
    uint32_t a;
    asm("{ .reg .u64 t; cvta.to.shared.u64 t, %1; cvt.u32.u64 %0, t; }" : "=r"(a) : "l"(p));
    return a;
}

#define LDSM4(r0, r1, r2, r3, addr) \
    asm volatile("ldmatrix.sync.aligned.m8n8.x4.shared.b16 {%0,%1,%2,%3}, [%4];" \
        : "=r"(r0), "=r"(r1), "=r"(r2), "=r"(r3) : "r"(addr))

#define MMA16816(d, a, b) \
    asm volatile("mma.sync.aligned.m16n8k16.row.col.f32.bf16.bf16.f32 " \
        "{%0,%1,%2,%3},{%4,%5,%6,%7},{%8,%9},{%0,%1,%2,%3};" \
        : "+f"((d)[0]), "+f"((d)[1]), "+f"((d)[2]), "+f"((d)[3]) \
        : "r"((a)[0]), "r"((a)[1]), "r"((a)[2]), "r"((a)[3]), "r"((b)[0]), "r"((b)[1]))

// ---------------------------------------------------------------------------
// prep_cb: codebook bf16 + norms + split-residual norms
// ---------------------------------------------------------------------------
__global__ void prep_cb_kernel(const float* __restrict__ cb) {
    __shared__ float red[256];
    int k = blockIdx.x, t = threadIdx.x;
    float v = cb[k * Dd + t];
    __nv_bfloat16 h0 = __float2bfloat16(v);
    g_c0[k * Dd + t] = h0;
    float dl = v - __bfloat162float(h0);
    red[t] = v * v;
    __syncthreads();
    for (int s = 128; s > 0; s >>= 1) { if (t < s) red[t] += red[t + s]; __syncthreads(); }
    if (t == 0) g_cn[k] = red[0];
    __syncthreads();
    red[t] = dl * dl;
    __syncthreads();
    for (int s = 128; s > 0; s >>= 1) { if (t < s) red[t] += red[t + s]; __syncthreads(); }
    if (t == 0) g_dcn[k] = sqrtf(red[0]);
}

// ---------------------------------------------------------------------------
// prep_z: transpose z [b][d][hw] -> m-major bf16 [m][d]
// ---------------------------------------------------------------------------
__global__ __launch_bounds__(256) void prep_z_kernel(const float* __restrict__ z) {
    __shared__ float tile[32][65];
    int bb = blockIdx.x;
    int b = bb >> 4;
    int hw0 = (bb & 15) << 6;
    int t = threadIdx.x;
    const float* zb = z + (size_t)b * (Dd * HWc) + hw0;
    size_t mbase = ((size_t)b * HWc + hw0) * Dd;
    for (int dg = 0; dg < 8; dg++) {
        #pragma unroll
        for (int i = t; i < 32 * 64; i += 256) {
            int d = i >> 6, m = i & 63;
            tile[d][m] = zb[(size_t)(dg * 32 + d) * HWc + m];
        }
        __syncthreads();
        {
            int m = t >> 2, c4 = t & 3;
            __align__(16) __nv_bfloat16 o0[8];
            #pragma unroll
            for (int u = 0; u < 8; u++)
                o0[u] = __float2bfloat16(tile[c4 * 8 + u][m]);
            *(uint4*)(g_z0 + mbase + (size_t)m * Dd + dg * 32 + c4 * 8) = *(const uint4*)o0;
        }
        __syncthreads();
    }
}

// ---------------------------------------------------------------------------
// vq: bf16 mma.sync estimate GEMM + windowed candidates + exact rescore
// grid = 512 CTAs x 256 threads
// ---------------------------------------------------------------------------
__global__ __launch_bounds__(256, 1)
void vq_kernel(const float* __restrict__ z, const float* __restrict__ cbf,
               float* __restrict__ out) {
    extern __shared__ char smraw[];
    uint32_t sb = smem_u32(smraw);
    uint32_t ab = (sb + 1023) & ~1023u;
    char* ap = smraw + (ab - sb);

    float* cn_s  = (float*)(ap + OFF_CN);
    float* DIST  = (float*)(ap + OFF_DIST);
    float* zz_s  = (float*)(ap + OFF_ZZ);
    float* red   = (float*)(ap + OFF_RED);
    float* rm_s  = (float*)(ap + OFF_RM);
    int*   cnt_s = (int*)(ap + OFF_CNT);
    unsigned short* list_s = (unsigned short*)(ap + OFF_LIST);
    int*   idx_s = (int*)(ap + OFF_IDX);
    float* W_s   = (float*)(ap + OFF_W);

    const int t = threadIdx.x;
    const int wid = t >> 5, lid = t & 31;
    const int mw = wid & 3;        // m-block (32 rows each)
    const int nw = wid >> 2;       // n-half (64 cols each)
    const int bb = blockIdx.x;
    const int b = bb >> 3;
    const int hw0 = (bb & 7) << 7;
    const int m0 = bb * 128;
    const float* zb = z + ((size_t)b * Dd) * HWc + hw0;

    const uint32_t abase = ab + OFF_A;
    const uint32_t bbase = ab + OFF_B;
    char* aP = ap + OFF_A;
    char* bP = ap + OFF_B;

    // ---- stage A (all k) into smem, SW128 per kc tile ----
    #pragma unroll
    for (int i = 0; i < 16; i++) {
        int lin = i * 256 + t;
        int kcI = lin >> 10, rem = lin & 1023, m = rem >> 3, u = rem & 7;
        uint4 v = *(const uint4*)(g_z0 + (size_t)(m0 + m) * Dd + kcI * 64 + u * 8);
        *(uint4*)(aP + kcI * 16384 + SWZ(m * 128 + u * 16)) = v;
    }
    // ---- stage B(0,0) into buf0 ----
    {
        #pragma unroll
        for (int i = 0; i < 4; i++) {
            int lin = i * 256 + t;
            int n = lin >> 3, u = lin & 7;
            uint4 v = *(const uint4*)(g_c0 + (size_t)n * Dd + u * 8);
            *(uint4*)(bP + SWZ(n * 128 + u * 16)) = v;
        }
    }

    // ---- query squared norms ----
    {
        int m = t & 127, half = t >> 7;
        const float* p = zb + (size_t)(half * 128) * HWc + m;
        float s = 0.f;
        #pragma unroll 8
        for (int d = 0; d < 128; d++) { float v = p[(size_t)d * HWc]; s = fmaf(v, v, s); }
        red[t] = s;
        __syncthreads();
        if (t < 128) zz_s[t] = red[t] + red[t + 128];
        __syncthreads();
    }
    // ---- cn + maxes ----
    float cmx = 0.f, dmx = 0.f;
    #pragma unroll
    for (int i = 0; i < 4; i++) {
        float c = g_cn[t + i * 256];
        cn_s[t + i * 256] = c;
        cmx = fmaxf(cmx, c);
        dmx = fmaxf(dmx, g_dcn[t + i * 256]);
    }
    red[t] = cmx; __syncthreads();
    for (int s = 128; s > 0; s >>= 1) { if (t < s) red[t] = fmaxf(red[t], red[t + s]); __syncthreads(); }
    float Cmax = sqrtf(red[0]);
    __syncthreads();
    red[t] = dmx; __syncthreads();
    for (int s = 128; s > 0; s >>= 1) { if (t < s) red[t] = fmaxf(red[t], red[t + s]); __syncthreads(); }
    float DCmax = red[0];
    __syncthreads();

    if (t < 128) W_s[t] = 4.f * sqrtf(zz_s[t]) * (0.00390625f * Cmax + 1.01f * DCmax) + 1e-3f;
    rm_s[t] = 3.4e38f;
    cnt_s[t] = 0;
    __syncthreads();

    // ldmatrix per-thread geometry
    const int g8 = lid & 7, sel = lid >> 3;
    const int aR0 = mw * 32 + (sel & 1) * 8 + g8;     // + mt*16
    const int aKo = (sel >> 1) * 16;
    const int bR0 = nw * 64 + (sel >> 1) * 8 + g8;    // + p*16
    const int bKo = (sel & 1) * 16;

    // ---- main loop: 8 n-chunks x 4 k-chunks, B double-buffered ----
    for (int nc = 0; nc < 8; nc++) {
        float acc[2][8][4];
        #pragma unroll
        for (int i = 0; i < 2; i++)
            #pragma unroll
            for (int j = 0; j < 8; j++)
                #pragma unroll
                for (int q = 0; q < 4; q++) acc[i][j][q] = 0.f;

        for (int kc = 0; kc < 4; kc++) {
            int stage = nc * 4 + kc;
            int cur = stage & 1;
            uint4 pf[4];
            bool hasNext = stage < 31;
            if (hasNext) {
                int ns = stage + 1;
                int nc2 = ns >> 2, kc2 = ns & 3;
                #pragma unroll
                for (int i = 0; i < 4; i++) {
                    int lin = i * 256 + t;
                    int n = lin >> 3, u = lin & 7;
                    pf[i] = *(const uint4*)(g_c0 + (size_t)(nc2 * 128 + n) * Dd + kc2 * 64 + u * 8);
                }
            }
            const uint32_t bcur = bbase + cur * 16384;
            const uint32_t acur = abase + kc * 16384;
            #pragma unroll
            for (int ks = 0; ks < 4; ks++) {
                uint32_t af[2][4];
                #pragma unroll
                for (int mt = 0; mt < 2; mt++) {
                    uint32_t addr = acur + SWZ((aR0 + mt * 16) * 128 + ks * 32 + aKo);
                    LDSM4(af[mt][0], af[mt][1], af[mt][2], af[mt][3], addr);
                }
                uint32_t bf[8][2];
                #pragma unroll
                for (int p = 0; p < 4; p++) {
                    uint32_t addr = bcur + SWZ((bR0 + p * 16) * 128 + ks * 32 + bKo);
                    LDSM4(bf[2 * p][0], bf[2 * p][1], bf[2 * p + 1][0], bf[2 * p + 1][1], addr);
                }
                #pragma unroll
                for (int mt = 0; mt < 2; mt++)
                    #pragma unroll
                    for (int nt = 0; nt < 8; nt++)
                        MMA16816(acc[mt][nt], af[mt], bf[nt]);
            }
            if (hasNext) {
                #pragma unroll
                for (int i = 0; i < 4; i++) {
                    int lin = i * 256 + t;
                    int n = lin >> 3, u = lin & 7;
                    *(uint4*)(bP + (cur ^ 1) * 16384 + SWZ(n * 128 + u * 16)) = pf[i];
                }
            }
            __syncthreads();
        }

        // ---- dump dots to smem ----
        {
            int lr = lid >> 2, lc2 = (lid & 3) * 2;
            #pragma unroll
            for (int mt = 0; mt < 2; mt++)
                #pragma unroll
                for (int nt = 0; nt < 8; nt++) {
                    int m = mw * 32 + mt * 16 + lr;
                    int col = nw * 64 + nt * 8 + lc2;
                    *(float2*)&DIST[m * 132 + col] = make_float2(acc[mt][nt][0], acc[mt][nt][1]);
                    *(float2*)&DIST[(m + 8) * 132 + col] = make_float2(acc[mt][nt][2], acc[mt][nt][3]);
                }
        }
        __syncthreads();

        // ---- windowed candidate scan (2 threads / query) ----
        {
            int q = t >> 1, half = t & 1;
            float rm = rm_s[t];
            int cnt = cnt_s[t];
            float W = W_s[q];
            const float* drow = DIST + q * 132 + half * 64;
            int jbase = nc * 128 + half * 64;
            #pragma unroll 8
            for (int i = 0; i < 64; i++) {
                float est = fmaf(-2.f, drow[i], cn_s[jbase + i]);
                if (est < rm + W) {
                    if (cnt < CAP) list_s[t * CAP + cnt] = (unsigned short)(jbase + i);
                    cnt++;
                }
                rm = fminf(rm, est);
            }
            rm_s[t] = rm;
            cnt_s[t] = cnt;
        }
        __syncthreads();
    }

    // ---- phase 2: exact rescoring of candidates (ascending j, strict <) ----
    if (t < 128) {
        int q = t;
        float zzq = zz_s[q];
        const float* zp = zb + q;
        auto exact = [&](int j) -> float {
            const float* crow = cbf + (size_t)j * Dd;
            float s0 = 0.f, s1 = 0.f, s2 = 0.f, s3 = 0.f;
            #pragma unroll 8
            for (int d = 0; d < Dd; d += 4) {
                float4 c4 = *(const float4*)(crow + d);
                s0 = fmaf(zp[(size_t)(d + 0) * HWc], c4.x, s0);
                s1 = fmaf(zp[(size_t)(d + 1) * HWc], c4.y, s1);
                s2 = fmaf(zp[(size_t)(d + 2) * HWc], c4.z, s2);
                s3 = fmaf(zp[(size_t)(d + 3) * HWc], c4.w, s3);
            }
            float dot = (s0 + s1) + (s2 + s3);
            float s = zzq + cn_s[j];
            return fmaf(-2.f, dot, s);
        };
        int na = cnt_s[2 * q], nb = cnt_s[2 * q + 1];
        float best = 3.4e38f;
        int bi = 0;
        if (na > CAP || nb > CAP) {
            for (int j = 0; j < Kc; j++) {
                float d = exact(j);
                if (d < best) { best = d; bi = j; }
            }
        } else {
            const unsigned short* La = list_s + (2 * q) * CAP;
            const unsigned short* Lb = list_s + (2 * q + 1) * CAP;
            int ia = 0, ib = 0;
            while (ia < na || ib < nb) {
                int j;
                if (ib >= nb || (ia < na && La[ia] < Lb[ib])) j = La[ia++];
                else j = Lb[ib++];
                float d = exact(j);
                if (d < best) { best = d; bi = j; }
            }
        }
        idx_s[q] = bi;
    }
    __syncthreads();

    // ---- outputs: quantized_st + loss partial (R1-proven epilogue) ----
    float* outq = out + ((size_t)b * Dd) * HWc + hw0;
    float lsum = 0.f;
    #pragma unroll 1
    for (int it = 0; it < 32; it++) {
        int lin = it * 256 + t;
        int d = lin >> 5, c4 = lin & 31;
        int mm = 4 * c4;
        float4 zv = *(const float4*)(zb + (size_t)d * HWc + mm);
        float q0 = cbf[(size_t)idx_s[mm + 0] * Dd + d];
        float q1 = cbf[(size_t)idx_s[mm + 1] * Dd + d];
        float q2 = cbf[(size_t)idx_s[mm + 2] * Dd + d];
        float q3 = cbf[(size_t)idx_s[mm + 3] * Dd + d];
        float f0 = q0 - zv.x, f1 = q1 - zv.y, f2 = q2 - zv.z, f3 = q3 - zv.w;
        float4 ov = make_float4(zv.x + f0, zv.y + f1, zv.z + f2, zv.w + f3);
        *(float4*)(outq + (size_t)d * HWc + mm) = ov;
        lsum += f0 * f0 + f1 * f1 + f2 * f2 + f3 * f3;
    }

    if (t < 128) out[16777216 + (size_t)bb * 128 + t] = (float)idx_s[t];

    red[t] = lsum;
    __syncthreads();
    for (int s = 128; s > 0; s >>= 1) { if (t < s) red[t] += red[t + s]; __syncthreads(); }
    if (t == 0) g_partials[bb] = red[0];
}

// ---------------------------------------------------------------------------
// loss reduction
// ---------------------------------------------------------------------------
__global__ void loss_kernel(float* __restrict__ out) {
    __shared__ float red[NBLK];
    int t = threadIdx.x;
    red[t] = g_partials[t];
    __syncthreads();
    for (int s = 256; s > 0; s >>= 1) { if (t < s) red[t] += red[t + s]; __syncthreads(); }
    if (t == 0) { float S = red[0]; out[16842752] = S * 0.25f + S; }
}

extern "C" void kernel_launch(void* const* d_in, const int* in_sizes, int n_in,
                              void* d_out, int out_size) {
    const float* z  = (const float*)d_in[0];
    const float* cb = (const float*)d_in[1];
    if (n_in >= 2 && in_sizes[0] == Kc * Dd) {
        z  = (const float*)d_in[1];
        cb = (const float*)d_in[0];
    }
    float* out = (float*)d_out;
    cudaFuncSetAttribute(vq_kernel, cudaFuncAttributeMaxDynamicSharedMemorySize, SMEM_BYTES);
    prep_cb_kernel<<<Kc, 256>>>(cb);
    prep_z_kernel<<<1024, 256>>>(z);
    vq_kernel<<<NBLK, 256, SMEM_BYTES>>>(z, cb, out);
    loss_kernel<<<1, NBLK>>>(out);
}